// round 6
// baseline (speedup 1.0000x reference)
#include <cuda_runtime.h>
#include <cuda_bf16.h>
#include <cstdint>

// Batched inverse of 3x3 upper-triangular matrices, rows of 9 fp32.
//   in : [a b c | . d e | . . f]
//   out: [1/a  -b/(ad)  (be-cd)/(adf) | 0  1/d  -e/(df) | 0 0 1/f]
//
// R6 probe: DRAM pinned at 81-82% across 4 kernel shapes; the only SM-side
// path not yet eliminated is the LSU/L1tex register load/store path (L1 at
// 59%). Replace ALL per-thread global traffic with bulk async copies:
//   - 1x cp.async.bulk global->shared (9216B) per CTA, mbarrier complete_tx
//   - compute in smem (1 row/thread, single rcp per row)
//   - 1x cp.async.bulk shared->global (9216B), bulk_group + wait_group.read
// 2 memory instructions per tile instead of ~1150 warp-instrs. If DRAM%
// rises, LSU was co-limiting; if neutral, we are at the HBM mix ceiling.
//
// Shape kept from the best kernel: 256 rows / 256 threads / ~9.3KB smem ->
// 8 CTAs/SM. Compute smem addressing word 9t+k, gcd(9,32)=1, conflict-free.

#define THREADS 256
#define ROWS_PER_BLOCK 256
#define FLOATS_PER_BLOCK (ROWS_PER_BLOCK * 9)   // 2304
#define TILE_BYTES (FLOATS_PER_BLOCK * 4)       // 9216

__device__ __forceinline__ void inv3_row(const float* __restrict__ p,
                                         float* __restrict__ q)
{
    float a = p[0], b = p[1], c = p[2];
    float d = p[4], e = p[5];
    float f = p[8];

    float ad = a * d;
    float df = d * f;
    float af = a * f;
    float ip = __frcp_rn(ad * f);      // single reciprocal: 1/(a d f)

    float ia  = df * ip;               // 1/a
    float id  = af * ip;               // 1/d
    float iff = ad * ip;               // 1/f
    float o01 = -(b * f) * ip;         // -b/(ad)
    float o12 = -(e * a) * ip;         // -e/(df)
    float o02 = (b * e - c * d) * ip;  // (be - cd)/(adf)

    q[0] = ia;
    q[1] = o01;
    q[2] = o02;
    q[3] = 0.0f;
    q[4] = id;
    q[5] = o12;
    q[6] = 0.0f;
    q[7] = 0.0f;
    q[8] = iff;
}

__global__ __launch_bounds__(THREADS, 8) void inv3_bulk_kernel(
    const float* __restrict__ in, float* __restrict__ out)
{
    __shared__ alignas(128) float s[FLOATS_PER_BLOCK];  // 9216 B
    __shared__ alignas(8) uint64_t mbar;

    const int t = threadIdx.x;
    const long long base = (long long)blockIdx.x * FLOATS_PER_BLOCK;

    uint32_t s_addr = (uint32_t)__cvta_generic_to_shared(s);
    uint32_t b_addr = (uint32_t)__cvta_generic_to_shared(&mbar);

    if (t == 0) {
        asm volatile("mbarrier.init.shared.b64 [%0], %1;"
                     :: "r"(b_addr), "r"(1) : "memory");
        // Order mbarrier init (generic proxy) before async-proxy use.
        asm volatile("fence.proxy.async.shared::cta;" ::: "memory");
        asm volatile("mbarrier.arrive.expect_tx.shared.b64 _, [%0], %1;"
                     :: "r"(b_addr), "r"(TILE_BYTES) : "memory");
        asm volatile(
            "cp.async.bulk.shared::cluster.global.mbarrier::complete_tx::bytes"
            " [%0], [%1], %2, [%3];"
            :: "r"(s_addr), "l"(in + base), "r"(TILE_BYTES), "r"(b_addr)
            : "memory");
    }
    __syncthreads();

    // All threads wait for the bulk load (phase 0 of a freshly-init barrier).
    {
        uint32_t done;
        asm volatile(
            "{\n\t.reg .pred p;\n\t"
            "mbarrier.try_wait.parity.acquire.cta.shared::cta.b64 p, [%1], 0;\n\t"
            "selp.b32 %0, 1, 0, p;\n\t}"
            : "=r"(done) : "r"(b_addr) : "memory");
        if (!done) {
            asm volatile(
                "{\n\t.reg .pred P1;\n\t"
                "WL_%=:\n\t"
                "mbarrier.try_wait.parity.acquire.cta.shared::cta.b64 P1, [%0], 0, 0x989680;\n\t"
                "@P1 bra.uni WD_%=;\n\t"
                "bra.uni WL_%=;\n\t"
                "WD_%=:\n\t}"
                :: "r"(b_addr) : "memory");
        }
    }

    // ---- Compute: 1 row per thread, in place in smem ----
    {
        float* p = &s[t * 9];
        inv3_row(p, p);
    }
    __syncthreads();

    // ---- Bulk store: shared -> global, single instruction ----
    if (t == 0) {
        // Order generic-proxy smem writes before the async-proxy bulk read.
        asm volatile("fence.proxy.async.shared::cta;" ::: "memory");
        asm volatile(
            "cp.async.bulk.global.shared::cta.bulk_group [%0], [%1], %2;"
            :: "l"(out + base), "r"(s_addr), "r"(TILE_BYTES) : "memory");
        asm volatile("cp.async.bulk.commit_group;" ::: "memory");
        // Wait until the bulk engine finished READING smem (not writing gmem)
        // so the CTA may exit and smem be reused safely.
        asm volatile("cp.async.bulk.wait_group.read 0;" ::: "memory");
    }
    __syncthreads();
}

// Scalar tail for rows not covered by full blocks (not hit for N=8388608).
__global__ void inv3_tail_kernel(const float* __restrict__ in,
                                 float* __restrict__ out, int nrows)
{
    int row = blockIdx.x * blockDim.x + threadIdx.x;
    if (row >= nrows) return;
    inv3_row(in + (long long)row * 9, out + (long long)row * 9);
}

extern "C" void kernel_launch(void* const* d_in, const int* in_sizes, int n_in,
                              void* d_out, int out_size)
{
    const float* x = (const float*)d_in[0];
    float* y = (float*)d_out;
    long long total_floats = in_sizes[0];
    long long nrows = total_floats / 9;

    long long nblocks = nrows / ROWS_PER_BLOCK;
    if (nblocks > 0) {
        inv3_bulk_kernel<<<(unsigned)nblocks, THREADS>>>(x, y);
    }
    long long done = nblocks * ROWS_PER_BLOCK;
    int rem = (int)(nrows - done);
    if (rem > 0) {
        inv3_tail_kernel<<<(rem + 255) / 256, 256>>>(
            x + done * 9, y + done * 9, rem);
    }
}